// round 15
// baseline (speedup 1.0000x reference)
#include <cuda_runtime.h>
#include <math.h>
#include <stdint.h>

#define DT 512
#define DB 256
#define DI 256
#define DH 256
#define DG 768
#define DP (DT * DB)

typedef unsigned long long u64;

// ---------------- device scratch ----------
__device__ int      g_src[DP];
__device__ int      g_order[DP];
__device__ int      g_len[DB];
__device__ int      g_maxlen;
__device__ int      g_ntrue;
__device__ unsigned g_barg[16 * 32];   // 16 group counters, 128B apart
__device__ float    g_h0[DB * DH];
__device__ float    g_h1[DB * DH];

// ---------------- f32x2 helpers ----------
__device__ __forceinline__ u64 pack2(float lo, float hi) {
    u64 r; asm("mov.b64 %0, {%1, %2};" : "=l"(r) : "f"(lo), "f"(hi)); return r;
}
__device__ __forceinline__ void unpack2(u64 v, float& lo, float& hi) {
    asm("mov.b64 {%0, %1}, %2;" : "=f"(lo), "=f"(hi) : "l"(v));
}
__device__ __forceinline__ void fma2(u64& d, u64 a, u64 b) {
    asm("fma.rn.f32x2 %0, %1, %2, %0;" : "+l"(d) : "l"(a), "l"(b));
}
__device__ __forceinline__ float tanh_ap(float x) {
    float r; asm("tanh.approx.f32 %0, %1;" : "=f"(r) : "f"(x)); return r;
}

// ---------------------------------------------------------------------------
// Kernel 1: lengths, packed mask, ranks, order[], src[]  (1 CTA, 1024 thr)
// ---------------------------------------------------------------------------
__global__ void k_prep(const int* __restrict__ mask) {
    __shared__ int sLen[DB];
    __shared__ int sWm[32], sWp[32];
    __shared__ int sMax;
    const int tid = threadIdx.x;
    if (tid < 512) g_barg[tid] = 0u;
    if (tid < DB) sLen[tid] = 0;
    if (tid == 0) sMax = 0;
    __syncthreads();
    {
        const int b = tid & 255;
        int acc = 0;
        for (int t = tid >> 8; t < DT; t += 4) acc += (mask[(t << 8) + b] != 0) ? 1 : 0;
        atomicAdd(&sLen[b], acc);
    }
    __syncthreads();
    if (tid < DB) { g_len[tid] = sLen[tid]; atomicMax(&sMax, sLen[tid]); }
    __syncthreads();
    if (tid == 0) g_maxlen = sMax;

    const int base = tid << 7;
    int cm = 0, cp = 0;
    #pragma unroll 4
    for (int i = 0; i < 128; i++) {
        const int p = base + i;
        cm += (mask[p] != 0) ? 1 : 0;
        cp += ((p >> 8) < sLen[p & 255]) ? 1 : 0;
    }
    const int lane = tid & 31, wid = tid >> 5;
    int im = cm, ip = cp;
    #pragma unroll
    for (int d = 1; d < 32; d <<= 1) {
        const int um = __shfl_up_sync(0xffffffffu, im, d);
        const int up = __shfl_up_sync(0xffffffffu, ip, d);
        if (lane >= d) { im += um; ip += up; }
    }
    if (lane == 31) { sWm[wid] = im; sWp[wid] = ip; }
    __syncthreads();
    if (wid == 0) {
        const int am = sWm[lane], ap = sWp[lane];
        int jm = am, jp = ap;
        #pragma unroll
        for (int d = 1; d < 32; d <<= 1) {
            const int um = __shfl_up_sync(0xffffffffu, jm, d);
            const int up = __shfl_up_sync(0xffffffffu, jp, d);
            if (lane >= d) { jm += um; jp += up; }
        }
        sWm[lane] = jm - am;
        sWp[lane] = jp - ap;
        if (lane == 31) g_ntrue = jm;
    }
    __syncthreads();

    int mrank = sWm[wid] + im - cm;
    int prank = sWp[wid] + ip - cp;
    for (int i = 0; i < 128; i++) {
        const int p  = base + i;
        const int mt = (mask[p] != 0) ? 1 : 0;
        const int pt = ((p >> 8) < sLen[p & 255]) ? 1 : 0;
        if (mt) g_order[mrank] = p;
        g_src[p] = pt ? prank : -1;
        mrank += mt; prank += pt;
    }
    __syncthreads();
    for (int i = 0; i < 128; i++) {
        const int p = base + i;
        const int k = g_src[p];
        if (k >= 0) g_src[p] = g_order[k];
    }
}

// ---------------------------------------------------------------------------
// Shared inner kloop: acc(j-pair, 3 gates) += row[k] * W[k] over K=256.
// row and W both in smem; row XOR-swizzled by hxor; W j-pair interleaved.
// ---------------------------------------------------------------------------
__device__ __forceinline__ void kloop256(
    const float* __restrict__ hrow, const int hxor,
    const float* __restrict__ wr, const float* __restrict__ wz,
    const float* __restrict__ wn,
    u64& ar, u64& az, u64& an) {
    #pragma unroll 8
    for (int i = 0; i < 64; i++) {
        const float4 hv = *(const float4*)(hrow + ((i ^ hxor) << 2));
        const int o = i << 3;
        const double2 r01 = *(const double2*)(wr + o);
        const double2 r23 = *(const double2*)(wr + o + 4);
        const double2 z01 = *(const double2*)(wz + o);
        const double2 z23 = *(const double2*)(wz + o + 4);
        const double2 n01 = *(const double2*)(wn + o);
        const double2 n23 = *(const double2*)(wn + o + 4);
        const u64 h0 = pack2(hv.x, hv.x), h1 = pack2(hv.y, hv.y);
        const u64 h2 = pack2(hv.z, hv.z), h3 = pack2(hv.w, hv.w);
        fma2(ar, h0, __double_as_longlong(r01.x));
        fma2(ar, h1, __double_as_longlong(r01.y));
        fma2(ar, h2, __double_as_longlong(r23.x));
        fma2(ar, h3, __double_as_longlong(r23.y));
        fma2(az, h0, __double_as_longlong(z01.x));
        fma2(az, h1, __double_as_longlong(z01.y));
        fma2(az, h2, __double_as_longlong(z23.x));
        fma2(az, h3, __double_as_longlong(z23.y));
        fma2(an, h0, __double_as_longlong(n01.x));
        fma2(an, h1, __double_as_longlong(n01.y));
        fma2(an, h2, __double_as_longlong(n23.x));
        fma2(an, h3, __double_as_longlong(n23.y));
    }
}

// ---------------------------------------------------------------------------
// Kernel 2: PERSISTENT fused recurrence. 128 CTAs (16 jt x 8 bt), 256 thr.
// R14 structure + gi GEMM fused into the barrier-wait window: after the
// arrive, each CTA gathers its 32 x-rows for step t+1 into smem and runs a
// second kloop (x . W_ih) producing next step's gi in registers — fully
// independent of the global barrier, so it hides the spin. k_gi and the
// 402MB g_gi buffer are gone.
// smem: W_hh 49.9KB | W_ih 49.9KB | h 32KB | x 32KB = 161.5KB -> 1 CTA/SM.
// ---------------------------------------------------------------------------
#define WSF   (24 * 520)                    // one W slice: 24 rows x (512+8)
#define HOFFS (2 * WSF)                     // floats before h tile
#define XOFFS (HOFFS + 32 * 256)
#define STP_SMEMB ((XOFFS + 32 * 256) * 4)  // 165376 B

extern __shared__ float s_stp[];

__global__ void __launch_bounds__(256, 1)
k_recp(const float* __restrict__ x,
       const float* __restrict__ Whh, const float* __restrict__ Wih,
       const float* __restrict__ bhh, const float* __restrict__ bih,
       float* __restrict__ out, const size_t oe) {
    const int tid = threadIdx.x;
    const int jp = tid >> 5, bl = tid & 31;
    const int jt = blockIdx.x & 15, bt = blockIdx.x >> 4;
    const int bglob = (bt << 5) + bl;
    const int j0 = (jt << 4) + (jp << 1);
    unsigned* bar = &g_barg[bt << 5];

    float* Ws = s_stp;                 // W_hh slice
    float* Wi = s_stp + WSF;           // W_ih slice
    float* Hs = s_stp + HOFFS;         // h tile (32 b x 256, swizzled)
    float* Xs = s_stp + XOFFS;         // x tile (32 b x 256, swizzled)

    // ---- both W slices -> smem ONCE, j-pair interleaved
    #pragma unroll
    for (int it = 0; it < 12; it++) {
        const int idx = tid + (it << 8);
        const int row = idx >> 6, f4 = idx & 63;
        const int g = row >> 4, jr = row & 15;
        const int jpl = jr >> 1, jl = jr & 1;
        const size_t goff = ((size_t)((g << 8) + (jt << 4) + jr) << 8) + (f4 << 2);
        const float4 vh = *(const float4*)(Whh + goff);
        const float4 vi = *(const float4*)(Wih + goff);
        float* rbh = Ws + (jpl * 3 + g) * 520 + jl;
        float* rbi = Wi + (jpl * 3 + g) * 520 + jl;
        rbh[(((f4 << 2) + 0) << 1)] = vh.x; rbi[(((f4 << 2) + 0) << 1)] = vi.x;
        rbh[(((f4 << 2) + 1) << 1)] = vh.y; rbi[(((f4 << 2) + 1) << 1)] = vi.y;
        rbh[(((f4 << 2) + 2) << 1)] = vh.z; rbi[(((f4 << 2) + 2) << 1)] = vi.z;
        rbh[(((f4 << 2) + 3) << 1)] = vh.w; rbi[(((f4 << 2) + 3) << 1)] = vi.w;
    }

    // loop-invariant scalars; group lmax over this bt's 32 columns
    int lmax = 0;
    #pragma unroll 8
    for (int i = 0; i < 32; i++) lmax = max(lmax, g_len[(bt << 5) + i]);
    const int ntrue = g_ntrue;
    const int blen  = g_len[bglob];
    const float2 bh_r = __ldg((const float2*)(bhh + j0));
    const float2 bh_z = __ldg((const float2*)(bhh + 256 + j0));
    const float2 bh_n = __ldg((const float2*)(bhh + 512 + j0));
    const float2 bi_r = __ldg((const float2*)(bih + j0));
    const float2 bi_z = __ldg((const float2*)(bih + 256 + j0));
    const float2 bi_n = __ldg((const float2*)(bih + 512 + j0));

    const float* wr = Ws + (jp * 3 + 0) * 520;
    const float* wz = Ws + (jp * 3 + 1) * 520;
    const float* wn = Ws + (jp * 3 + 2) * 520;
    const float* ir = Wi + (jp * 3 + 0) * 520;
    const float* iz = Wi + (jp * 3 + 1) * 520;
    const float* in_ = Wi + (jp * 3 + 2) * 520;
    const float* hrow = Hs + (bl << 8);
    const float* xrow = Xs + (bl << 8);
    const int hxor = bl & 7;

    // ---- gi + dest for step 0: gather x rows, sync, kloop
    u64 gar = 0ull, gaz = 0ull, gan = 0ull;
    int p_dest;
    {
        const int tb = bt << 5;
        #pragma unroll
        for (int it = 0; it < 8; it++) {
            const int idx = tid + (it << 8);
            const int b = idx >> 6, ub = idx & 63;
            int srow = __ldg(&g_src[tb + b]);
            srow = (srow < 0) ? 0 : srow;
            const float4 v = *(const float4*)(x + ((size_t)srow << 8) + (ub << 2));
            *(float4*)(Xs + (b << 8) + ((ub ^ (b & 7)) << 2)) = v;
        }
        p_dest = ((0 < blen) && (bglob < ntrue)) ? __ldg(&g_order[bglob]) : -1;
        __syncthreads();
        kloop256(xrow, hxor, ir, iz, in_, gar, gaz, gan);
    }

    for (int t = 0; t < lmax; t++) {
        const float* __restrict__ hin  = (t & 1) ? g_h1 : g_h0;
        float* __restrict__       hout = (t & 1) ? g_h0 : g_h1;

        const int valid = (t < blen) ? 1 : 0;
        const int dest  = p_dest;
        // unpack this step's gi from the fused GEMM accumulators
        float gir0, gir1, giz0, giz1, gin0, gin1;
        unpack2(gar, gir0, gir1);
        unpack2(gaz, giz0, giz1);
        unpack2(gan, gin0, gin1);
        const float2 hold = *(const float2*)(hin + ((size_t)bglob << 8) + j0);

        // h tile -> smem, swizzled: unit u -> u ^ (b&7)
        #pragma unroll
        for (int it = 0; it < 8; it++) {
            const int idx = tid + (it << 8);
            const int b = idx >> 6, ub = idx & 63;
            const float4 v = *(const float4*)(hin + ((size_t)((bt << 5) + b) << 8) + (ub << 2));
            *(float4*)(Hs + (b << 8) + ((ub ^ (b & 7)) << 2)) = v;
        }
        __syncthreads();

        u64 ar = 0ull, az = 0ull, an = 0ull;
        kloop256(hrow, hxor, wr, wz, wn, ar, az, an);

        float ghr0, ghr1, ghz0, ghz1, ghn0, ghn1;
        unpack2(ar, ghr0, ghr1);
        unpack2(az, ghz0, ghz1);
        unpack2(an, ghn0, ghn1);

        float hn0, hn1;
        {
            const float r0 = 1.f / (1.f + __expf(-(gir0 + bi_r.x + ghr0 + bh_r.x)));
            const float z0 = 1.f / (1.f + __expf(-(giz0 + bi_z.x + ghz0 + bh_z.x)));
            const float n0 = tanh_ap(gin0 + bi_n.x + r0 * (ghn0 + bh_n.x));
            hn0 = (1.f - z0) * n0 + z0 * hold.x;
            const float r1 = 1.f / (1.f + __expf(-(gir1 + bi_r.y + ghr1 + bh_r.y)));
            const float z1 = 1.f / (1.f + __expf(-(giz1 + bi_z.y + ghz1 + bh_z.y)));
            const float n1 = tanh_ap(gin1 + bi_n.y + r1 * (ghn1 + bh_n.y));
            hn1 = (1.f - z1) * n1 + z1 * hold.y;
        }
        if (!valid) { hn0 = hold.x; hn1 = hold.y; }

        // hout store MUST precede the release (peer CTAs read it next step)
        *(float2*)(hout + ((size_t)bglob << 8) + j0) = make_float2(hn0, hn1);

        __syncthreads();
        if (tid == 0) {
            asm volatile("red.release.gpu.global.add.u32 [%0], 1;"
                         :: "l"(bar) : "memory");
        }

        // ======== barrier-hidden window: independent work ========
        // (a) scattered out store (no in-kernel consumer)
        if (dest >= 0) {
            const size_t o = ((size_t)dest << 8) + j0;
            if (o + 1 < oe) *(float2*)(out + o) = make_float2(hn0, hn1);
        }
        // (b) gather x rows for t+1 and compute next gi (x . W_ih)
        gar = 0ull; gaz = 0ull; gan = 0ull;
        const int tn = t + 1;
        if (tn < lmax) {
            const int tb = (tn << 8) + (bt << 5);
            #pragma unroll
            for (int it = 0; it < 8; it++) {
                const int idx = tid + (it << 8);
                const int b = idx >> 6, ub = idx & 63;
                int srow = __ldg(&g_src[tb + b]);
                srow = (srow < 0) ? 0 : srow;
                const float4 v = *(const float4*)(x + ((size_t)srow << 8) + (ub << 2));
                *(float4*)(Xs + (b << 8) + ((ub ^ (b & 7)) << 2)) = v;
            }
            const int nflat = tb + bl;
            p_dest = ((tn < blen) && (nflat < ntrue)) ? __ldg(&g_order[nflat]) : -1;
            __syncthreads();                    // Xs visible CTA-wide
            kloop256(xrow, hxor, ir, iz, in_, gar, gaz, gan);
        }
        // =========================================================

        if (tid == 0) {
            const unsigned tgt = 16u * (unsigned)(t + 1);
            unsigned v;
            do {
                asm volatile("ld.acquire.gpu.global.u32 %0, [%1];"
                             : "=r"(v) : "l"(bar));
            } while (v < tgt);
        }
        __syncthreads();
    }

    // final hidden state for this bt-slice (written by jt==0 CTA of the group)
    if (jt == 0) {
        const float* hf = (lmax & 1) ? g_h1 : g_h0;
        const size_t obase = (size_t)DP << 8;
        for (int idx = tid; idx < 32 * 64; idx += 256) {
            const int b  = (bt << 5) + (idx >> 6);
            const int kq = (idx & 63) << 2;
            const size_t o = obase + ((size_t)b << 8) + kq;
            const float4 v = *(const float4*)(hf + ((size_t)b << 8) + kq);
            if (o + 3 < oe) *(float4*)(out + o) = v;
        }
    }
}

// ---------------------------------------------------------------------------
// Small helpers
// ---------------------------------------------------------------------------
__global__ void k_zero4(float4* __restrict__ out, const size_t n4) {
    size_t i = (size_t)blockIdx.x * blockDim.x + threadIdx.x;
    const size_t stride = (size_t)gridDim.x * blockDim.x;
    const float4 z = make_float4(0.f, 0.f, 0.f, 0.f);
    for (; i < n4; i += stride) out[i] = z;
}

__global__ void k_init(const float* __restrict__ hx) {
    const int i = blockIdx.x * blockDim.x + threadIdx.x;
    if (i < DB * DH) g_h0[i] = hx[i];
}

// ---------------------------------------------------------------------------
extern "C" void kernel_launch(void* const* d_in, const int* in_sizes, int n_in,
                              void* d_out, int out_size) {
    const float* x    = (const float*)d_in[0];
    const float* hx   = (const float*)d_in[1];
    const int*   mask = (const int*)  d_in[2];
    const float* Wih  = (const float*)d_in[3];
    const float* Whh  = (const float*)d_in[4];
    const float* bih  = (const float*)d_in[5];
    const float* bhh  = (const float*)d_in[6];
    float* out = (float*)d_out;
    const size_t oe = (size_t)out_size;

    static int s_attr_done = 0;
    if (!s_attr_done) {
        cudaFuncSetAttribute(k_recp, cudaFuncAttributeMaxDynamicSharedMemorySize,
                             STP_SMEMB);
        s_attr_done = 1;
    }

    k_prep<<<1, 1024>>>(mask);
    k_zero4<<<1024, 256>>>((float4*)out, oe >> 2);
    k_init<<<64, 1024>>>(hx);
    k_recp<<<128, 256, STP_SMEMB>>>(x, Whh, Wih, bhh, bih, out, oe);
}

// round 16
// speedup vs baseline: 1.0118x; 1.0118x over previous
#include <cuda_runtime.h>
#include <math.h>
#include <stdint.h>

#define DT 512
#define DB 256
#define DI 256
#define DH 256
#define DG 768
#define DP (DT * DB)

typedef unsigned long long u64;

// ---------------- device scratch ----------
__device__ int      g_src[DP];
__device__ int      g_order[DP];
__device__ int      g_len[DB];
__device__ int      g_maxlen;
__device__ int      g_ntrue;
__device__ unsigned g_barg[16 * 32];   // 16 group counters, 128B apart
__device__ float    g_h0[DB * DH];
__device__ float    g_h1[DB * DH];

// ---------------- f32x2 helpers ----------
__device__ __forceinline__ u64 pack2(float lo, float hi) {
    u64 r; asm("mov.b64 %0, {%1, %2};" : "=l"(r) : "f"(lo), "f"(hi)); return r;
}
__device__ __forceinline__ void unpack2(u64 v, float& lo, float& hi) {
    asm("mov.b64 {%0, %1}, %2;" : "=f"(lo), "=f"(hi) : "l"(v));
}
__device__ __forceinline__ void fma2(u64& d, u64 a, u64 b) {
    asm("fma.rn.f32x2 %0, %1, %2, %0;" : "+l"(d) : "l"(a), "l"(b));
}
__device__ __forceinline__ float tanh_ap(float x) {
    float r; asm("tanh.approx.f32 %0, %1;" : "=f"(r) : "f"(x)); return r;
}

// ---------------------------------------------------------------------------
// Kernel 1: lengths, packed mask, ranks, order[], src[]  (1 CTA, 1024 thr)
// ---------------------------------------------------------------------------
__global__ void k_prep(const int* __restrict__ mask) {
    __shared__ int sLen[DB];
    __shared__ int sWm[32], sWp[32];
    __shared__ int sMax;
    const int tid = threadIdx.x;
    if (tid < 512) g_barg[tid] = 0u;
    if (tid < DB) sLen[tid] = 0;
    if (tid == 0) sMax = 0;
    __syncthreads();
    {
        const int b = tid & 255;
        int acc = 0;
        for (int t = tid >> 8; t < DT; t += 4) acc += (mask[(t << 8) + b] != 0) ? 1 : 0;
        atomicAdd(&sLen[b], acc);
    }
    __syncthreads();
    if (tid < DB) { g_len[tid] = sLen[tid]; atomicMax(&sMax, sLen[tid]); }
    __syncthreads();
    if (tid == 0) g_maxlen = sMax;

    const int base = tid << 7;
    int cm = 0, cp = 0;
    #pragma unroll 4
    for (int i = 0; i < 128; i++) {
        const int p = base + i;
        cm += (mask[p] != 0) ? 1 : 0;
        cp += ((p >> 8) < sLen[p & 255]) ? 1 : 0;
    }
    const int lane = tid & 31, wid = tid >> 5;
    int im = cm, ip = cp;
    #pragma unroll
    for (int d = 1; d < 32; d <<= 1) {
        const int um = __shfl_up_sync(0xffffffffu, im, d);
        const int up = __shfl_up_sync(0xffffffffu, ip, d);
        if (lane >= d) { im += um; ip += up; }
    }
    if (lane == 31) { sWm[wid] = im; sWp[wid] = ip; }
    __syncthreads();
    if (wid == 0) {
        const int am = sWm[lane], ap = sWp[lane];
        int jm = am, jp = ap;
        #pragma unroll
        for (int d = 1; d < 32; d <<= 1) {
            const int um = __shfl_up_sync(0xffffffffu, jm, d);
            const int up = __shfl_up_sync(0xffffffffu, jp, d);
            if (lane >= d) { jm += um; jp += up; }
        }
        sWm[lane] = jm - am;
        sWp[lane] = jp - ap;
        if (lane == 31) g_ntrue = jm;
    }
    __syncthreads();

    int mrank = sWm[wid] + im - cm;
    int prank = sWp[wid] + ip - cp;
    for (int i = 0; i < 128; i++) {
        const int p  = base + i;
        const int mt = (mask[p] != 0) ? 1 : 0;
        const int pt = ((p >> 8) < sLen[p & 255]) ? 1 : 0;
        if (mt) g_order[mrank] = p;
        g_src[p] = pt ? prank : -1;
        mrank += mt; prank += pt;
    }
    __syncthreads();
    for (int i = 0; i < 128; i++) {
        const int p = base + i;
        const int k = g_src[p];
        if (k >= 0) g_src[p] = g_order[k];
    }
}

// ---------------------------------------------------------------------------
// Shared inner kloop: acc(j-pair, 3 gates) += row[k] * W[k] over K=256.
// ---------------------------------------------------------------------------
__device__ __forceinline__ void kloop256(
    const float* __restrict__ hrow, const int hxor,
    const float* __restrict__ wr, const float* __restrict__ wz,
    const float* __restrict__ wn,
    u64& ar, u64& az, u64& an) {
    #pragma unroll 8
    for (int i = 0; i < 64; i++) {
        const float4 hv = *(const float4*)(hrow + ((i ^ hxor) << 2));
        const int o = i << 3;
        const double2 r01 = *(const double2*)(wr + o);
        const double2 r23 = *(const double2*)(wr + o + 4);
        const double2 z01 = *(const double2*)(wz + o);
        const double2 z23 = *(const double2*)(wz + o + 4);
        const double2 n01 = *(const double2*)(wn + o);
        const double2 n23 = *(const double2*)(wn + o + 4);
        const u64 h0 = pack2(hv.x, hv.x), h1 = pack2(hv.y, hv.y);
        const u64 h2 = pack2(hv.z, hv.z), h3 = pack2(hv.w, hv.w);
        fma2(ar, h0, __double_as_longlong(r01.x));
        fma2(ar, h1, __double_as_longlong(r01.y));
        fma2(ar, h2, __double_as_longlong(r23.x));
        fma2(ar, h3, __double_as_longlong(r23.y));
        fma2(az, h0, __double_as_longlong(z01.x));
        fma2(az, h1, __double_as_longlong(z01.y));
        fma2(az, h2, __double_as_longlong(z23.x));
        fma2(az, h3, __double_as_longlong(z23.y));
        fma2(an, h0, __double_as_longlong(n01.x));
        fma2(an, h1, __double_as_longlong(n01.y));
        fma2(an, h2, __double_as_longlong(n23.x));
        fma2(an, h3, __double_as_longlong(n23.y));
    }
}

// ---------------------------------------------------------------------------
// Kernel 2: PERSISTENT warp-specialized recurrence. 128 CTAs (16jt x 8bt),
// 512 threads. Warps 0-7: R14 recurrence, unchanged datapath. Warps 8-15:
// gi producers — gather x rows for t+1, kloop vs resident W_ih, write a
// double-buffered 6KB gi tile in smem. Named barrier 1 = rec-internal,
// 2 = producer-internal; one joint __syncthreads per step. gi buffer parity:
// rec reads buf t&1 (written at window t-1); producers write buf (t+1)&1.
// smem: W_hh 49.9K | W_ih 49.9K | h 32K | x 32K | gi 12K = 173.5KB.
// ---------------------------------------------------------------------------
#define WSF    (24 * 520)                   // one W slice (floats)
#define HOFFS  (2 * WSF)                    // 24960
#define XOFFS  (HOFFS + 32 * 256)           // 33152
#define GOFFS  (XOFFS + 32 * 256)           // 41344
#define STP_SMEMB ((GOFFS + 2 * 1536) * 4)  // 177664 B

extern __shared__ float s_stp[];

__global__ void __launch_bounds__(512, 1)
k_recp(const float* __restrict__ x,
       const float* __restrict__ Whh, const float* __restrict__ Wih,
       const float* __restrict__ bhh, const float* __restrict__ bih,
       float* __restrict__ out, const size_t oe) {
    const int tid  = threadIdx.x;
    const int rec  = (tid < 256);
    const int rtid = tid & 255;                 // role-local id
    const int jp = rtid >> 5, bl = rtid & 31;
    const int jt = blockIdx.x & 15, bt = blockIdx.x >> 4;
    const int bglob = (bt << 5) + bl;
    const int j0 = (jt << 4) + (jp << 1);
    unsigned* bar = &g_barg[bt << 5];

    float* Ws = s_stp;                 // W_hh slice
    float* Wi = s_stp + WSF;           // W_ih slice
    float* Hs = s_stp + HOFFS;         // h tile (32 b x 256, swizzled)
    float* Xs = s_stp + XOFFS;         // x tile (32 b x 256, swizzled)
    float* Gs = s_stp + GOFFS;         // gi tiles: 2 x [32 b][3g x 16j]

    // ---- both W slices -> smem ONCE (all 512 threads), j-pair interleaved
    #pragma unroll
    for (int it = 0; it < 6; it++) {
        const int idx = tid + (it << 9);
        const int row = idx >> 6, f4 = idx & 63;
        const int g = row >> 4, jr = row & 15;
        const int jpl = jr >> 1, jl = jr & 1;
        const size_t goff = ((size_t)((g << 8) + (jt << 4) + jr) << 8) + (f4 << 2);
        const float4 vh = *(const float4*)(Whh + goff);
        const float4 vi = *(const float4*)(Wih + goff);
        float* rbh = Ws + (jpl * 3 + g) * 520 + jl;
        float* rbi = Wi + (jpl * 3 + g) * 520 + jl;
        rbh[(((f4 << 2) + 0) << 1)] = vh.x; rbi[(((f4 << 2) + 0) << 1)] = vi.x;
        rbh[(((f4 << 2) + 1) << 1)] = vh.y; rbi[(((f4 << 2) + 1) << 1)] = vi.y;
        rbh[(((f4 << 2) + 2) << 1)] = vh.z; rbi[(((f4 << 2) + 2) << 1)] = vi.z;
        rbh[(((f4 << 2) + 3) << 1)] = vh.w; rbi[(((f4 << 2) + 3) << 1)] = vi.w;
    }

    // loop-invariant scalars
    int lmax = 0;
    #pragma unroll 8
    for (int i = 0; i < 32; i++) lmax = max(lmax, g_len[(bt << 5) + i]);
    const int ntrue = g_ntrue;
    const int blen  = g_len[bglob];
    const int hxor  = bl & 7;

    // role-specific pointers
    const float* wr = Ws + (jp * 3 + 0) * 520;
    const float* wz = Ws + (jp * 3 + 1) * 520;
    const float* wn = Ws + (jp * 3 + 2) * 520;
    const float* ir = Wi + (jp * 3 + 0) * 520;
    const float* iz = Wi + (jp * 3 + 1) * 520;
    const float* in_ = Wi + (jp * 3 + 2) * 520;
    const float* hrow = Hs + (bl << 8);
    const float* xrow = Xs + (bl << 8);
    float* grow = Gs + bl * 48 + (jp << 1);    // + buf*1536 + gate*16

    const float2 bh_r = __ldg((const float2*)(bhh + j0));
    const float2 bh_z = __ldg((const float2*)(bhh + 256 + j0));
    const float2 bh_n = __ldg((const float2*)(bhh + 512 + j0));
    const float2 bi_r = __ldg((const float2*)(bih + j0));
    const float2 bi_z = __ldg((const float2*)(bih + 256 + j0));
    const float2 bi_n = __ldg((const float2*)(bih + 512 + j0));

    __syncthreads();   // W slices ready

    // ---- prologue: producers build gi buf 0 (t = 0); rec prefetches dest
    int p_dest = -1;
    if (rec) {
        p_dest = ((0 < blen) && (bglob < ntrue)) ? __ldg(&g_order[bglob]) : -1;
    } else {
        const int tb = bt << 5;
        #pragma unroll
        for (int it = 0; it < 8; it++) {
            const int idx = rtid + (it << 8);
            const int b = idx >> 6, ub = idx & 63;
            int srow = __ldg(&g_src[tb + b]);
            srow = (srow < 0) ? 0 : srow;
            const float4 v = *(const float4*)(x + ((size_t)srow << 8) + (ub << 2));
            *(float4*)(Xs + (b << 8) + ((ub ^ (b & 7)) << 2)) = v;
        }
        asm volatile("bar.sync 2, 256;" ::: "memory");
        u64 gar = 0ull, gaz = 0ull, gan = 0ull;
        kloop256(xrow, hxor, ir, iz, in_, gar, gaz, gan);
        *(u64*)(grow + 0)  = gar;
        *(u64*)(grow + 16) = gaz;
        *(u64*)(grow + 32) = gan;
    }
    __syncthreads();   // gi buf 0 visible to rec warps

    for (int t = 0; t < lmax; t++) {
        if (rec) {
            // ================= recurrence warps (R14 datapath) =============
            const float* __restrict__ hin  = (t & 1) ? g_h1 : g_h0;
            float* __restrict__       hout = (t & 1) ? g_h0 : g_h1;
            const int valid = (t < blen) ? 1 : 0;
            const int dest  = p_dest;
            const float2 hold = *(const float2*)(hin + ((size_t)bglob << 8) + j0);

            #pragma unroll
            for (int it = 0; it < 8; it++) {
                const int idx = rtid + (it << 8);
                const int b = idx >> 6, ub = idx & 63;
                const float4 v = *(const float4*)(hin +
                    ((size_t)((bt << 5) + b) << 8) + (ub << 2));
                *(float4*)(Hs + (b << 8) + ((ub ^ (b & 7)) << 2)) = v;
            }
            asm volatile("bar.sync 1, 256;" ::: "memory");

            u64 ar = 0ull, az = 0ull, an = 0ull;
            kloop256(hrow, hxor, wr, wz, wn, ar, az, an);

            // gi from producer tile (buf t&1, written at window t-1)
            const float* gf = Gs + ((t & 1) * 1536) + bl * 48 + (jp << 1);
            const float2 gi_r = *(const float2*)(gf + 0);
            const float2 gi_z = *(const float2*)(gf + 16);
            const float2 gi_n = *(const float2*)(gf + 32);

            float ghr0, ghr1, ghz0, ghz1, ghn0, ghn1;
            unpack2(ar, ghr0, ghr1);
            unpack2(az, ghz0, ghz1);
            unpack2(an, ghn0, ghn1);

            float hn0, hn1;
            {
                const float r0 = 1.f / (1.f + __expf(-(gi_r.x + bi_r.x + ghr0 + bh_r.x)));
                const float z0 = 1.f / (1.f + __expf(-(gi_z.x + bi_z.x + ghz0 + bh_z.x)));
                const float n0 = tanh_ap(gi_n.x + bi_n.x + r0 * (ghn0 + bh_n.x));
                hn0 = (1.f - z0) * n0 + z0 * hold.x;
                const float r1 = 1.f / (1.f + __expf(-(gi_r.y + bi_r.y + ghr1 + bh_r.y)));
                const float z1 = 1.f / (1.f + __expf(-(gi_z.y + bi_z.y + ghz1 + bh_z.y)));
                const float n1 = tanh_ap(gi_n.y + bi_n.y + r1 * (ghn1 + bh_n.y));
                hn1 = (1.f - z1) * n1 + z1 * hold.y;
            }
            if (!valid) { hn0 = hold.x; hn1 = hold.y; }

            *(float2*)(hout + ((size_t)bglob << 8) + j0) = make_float2(hn0, hn1);

            asm volatile("bar.sync 1, 256;" ::: "memory");
            if (tid == 0) {
                asm volatile("red.release.gpu.global.add.u32 [%0], 1;"
                             :: "l"(bar) : "memory");
            }

            // barrier-hidden window (rec side): scatter + dest prefetch
            if (dest >= 0) {
                const size_t o = ((size_t)dest << 8) + j0;
                if (o + 1 < oe) *(float2*)(out + o) = make_float2(hn0, hn1);
            }
            if (t + 1 < lmax) {
                const int nflat = ((t + 1) << 8) + bglob;
                p_dest = ((t + 1 < blen) && (nflat < ntrue))
                         ? __ldg(&g_order[nflat]) : -1;
            }

            if (tid == 0) {
                const unsigned tgt = 16u * (unsigned)(t + 1);
                unsigned v;
                do {
                    asm volatile("ld.acquire.gpu.global.u32 %0, [%1];"
                                 : "=r"(v) : "l"(bar));
                } while (v < tgt);
            }
        } else {
            // ================= gi producer warps: build gi for t+1 =========
            const int tn = t + 1;
            if (tn < lmax) {
                const int tb = (tn << 8) + (bt << 5);
                #pragma unroll
                for (int it = 0; it < 8; it++) {
                    const int idx = rtid + (it << 8);
                    const int b = idx >> 6, ub = idx & 63;
                    int srow = __ldg(&g_src[tb + b]);
                    srow = (srow < 0) ? 0 : srow;
                    const float4 v = *(const float4*)(x + ((size_t)srow << 8) + (ub << 2));
                    *(float4*)(Xs + (b << 8) + ((ub ^ (b & 7)) << 2)) = v;
                }
                asm volatile("bar.sync 2, 256;" ::: "memory");
                u64 gar = 0ull, gaz = 0ull, gan = 0ull;
                kloop256(xrow, hxor, ir, iz, in_, gar, gaz, gan);
                float* gw = grow + ((tn & 1) * 1536);
                *(u64*)(gw + 0)  = gar;
                *(u64*)(gw + 16) = gaz;
                *(u64*)(gw + 32) = gan;
            }
        }
        __syncthreads();   // step boundary: gi handoff + barrier release seen
    }

    // final hidden state for this bt-slice (jt==0 CTA, all 512 threads)
    if (jt == 0) {
        const float* hf = (lmax & 1) ? g_h1 : g_h0;
        const size_t obase = (size_t)DP << 8;
        for (int idx = tid; idx < 32 * 64; idx += 512) {
            const int b  = (bt << 5) + (idx >> 6);
            const int kq = (idx & 63) << 2;
            const size_t o = obase + ((size_t)b << 8) + kq;
            const float4 v = *(const float4*)(hf + ((size_t)b << 8) + kq);
            if (o + 3 < oe) *(float4*)(out + o) = v;
        }
    }
}

// ---------------------------------------------------------------------------
// Small helpers
// ---------------------------------------------------------------------------
__global__ void k_zero4(float4* __restrict__ out, const size_t n4) {
    size_t i = (size_t)blockIdx.x * blockDim.x + threadIdx.x;
    const size_t stride = (size_t)gridDim.x * blockDim.x;
    const float4 z = make_float4(0.f, 0.f, 0.f, 0.f);
    for (; i < n4; i += stride) out[i] = z;
}

__global__ void k_init(const float* __restrict__ hx) {
    const int i = blockIdx.x * blockDim.x + threadIdx.x;
    if (i < DB * DH) g_h0[i] = hx[i];
}

// ---------------------------------------------------------------------------
extern "C" void kernel_launch(void* const* d_in, const int* in_sizes, int n_in,
                              void* d_out, int out_size) {
    const float* x    = (const float*)d_in[0];
    const float* hx   = (const float*)d_in[1];
    const int*   mask = (const int*)  d_in[2];
    const float* Wih  = (const float*)d_in[3];
    const float* Whh  = (const float*)d_in[4];
    const float* bih  = (const float*)d_in[5];
    const float* bhh  = (const float*)d_in[6];
    float* out = (float*)d_out;
    const size_t oe = (size_t)out_size;

    static int s_attr_done = 0;
    if (!s_attr_done) {
        cudaFuncSetAttribute(k_recp, cudaFuncAttributeMaxDynamicSharedMemorySize,
                             STP_SMEMB);
        s_attr_done = 1;
    }

    k_prep<<<1, 1024>>>(mask);
    k_zero4<<<1024, 256>>>((float4*)out, oe >> 2);
    k_init<<<64, 1024>>>(hx);
    k_recp<<<128, 512, STP_SMEMB>>>(x, Whh, Wih, bhh, bih, out, oe);
}